// round 8
// baseline (speedup 1.0000x reference)
#include <cuda_runtime.h>

#define BLOCK   128
#define WPB     4
#define NSM     152
#define OCC     6
#define NBLOCKS (NSM * OCC)          // 912
#define NWARPS  (NBLOCKS * WPB)      // 3648 chunks, 1 per warp
#define WARM    12
#define PSP     36

typedef unsigned long long u64;

__device__ __forceinline__ u64 pk2(float a, float b) {
    u64 r; asm("mov.b64 %0, {%1,%2};" : "=l"(r) : "f"(a), "f"(b)); return r;
}
__device__ __forceinline__ void unpk2(float& a, float& b, u64 r) {
    asm("mov.b64 {%0,%1}, %2;" : "=f"(a), "=f"(b) : "l"(r));
}
__device__ __forceinline__ u64 fma2(u64 a, u64 b, u64 c) {
    u64 d; asm("fma.rn.f32x2 %0, %1, %2, %3;" : "=l"(d) : "l"(a), "l"(b), "l"(c)); return d;
}
__device__ __forceinline__ float ftanh(float x) {
    float r; asm("tanh.approx.f32 %0, %1;" : "=f"(r) : "f"(x)); return r;
}
__device__ __forceinline__ void cpa16(unsigned d, const void* s) {
    asm volatile("cp.async.ca.shared.global [%0], [%1], 16;" :: "r"(d), "l"(s));
}
__device__ __forceinline__ void cpacommit() { asm volatile("cp.async.commit_group;"); }
__device__ __forceinline__ void cpawait0()  { asm volatile("cp.async.wait_group 0;"); }

__global__ void __launch_bounds__(BLOCK, OCC) rnn_scan_kernel(
    const float* __restrict__ x, const float* __restrict__ weight,
    const float* __restrict__ weight_y, const float* __restrict__ bias,
    const float* __restrict__ weight_ln, const float* __restrict__ bias_ln,
    float* __restrict__ out, int B, int L)
{
    __shared__ __align__(16) float xs[WPB][2][16][16];    // x tiles, double-buffered
    __shared__ __align__(16) float ps[WPB][2][16][PSP];   // partials, double-buffered

    const int w    = threadIdx.x >> 5;
    const int lane = threadIdx.x & 31;
    const int wid  = blockIdx.x * WPB + w;
    const int start = wid * L;
    if (start >= B) return;
    const int tstop = min(start + L, B);
    const int t0    = max(0, start - WARM);   // contraction warmup (<=0.25^12)
    const int nt    = (tstop - t0 + 15) >> 4;

    // sigma(y) = 0.5 + 0.5*tanh(y/2); z = y/2; state t = tanh(z):
    //   z = (0.5*bias + 0.25*wy_h) + x·(0.5 W) + (0.25*wy_h)*t
    const float SC = 0.5f;

    // Lane owns hidden (h0,h1)=(2l,2l+1); crossed-half chains: x multiplier is
    // the natural pair {x_2k,x_2k+1}: z[h0]=c0.lo+c1.hi, z[h1]=c1.lo+c0.hi.
    const int h0 = 2 * lane, h1 = 2 * lane + 1;
    u64 w0k[8], w1k[8];
#pragma unroll
    for (int k = 0; k < 8; k++) {
        const float* r0 = weight + (2 * k) * 64;
        const float* r1 = weight + (2 * k + 1) * 64;
        w0k[k] = pk2(SC * r0[h0], SC * r1[h1]);
        w1k[k] = pk2(SC * r0[h1], SC * r1[h0]);
    }
    const float wyt0 = 0.25f * weight_y[h0];
    const float wyt1 = 0.25f * weight_y[h1];
    const float hl0  = 0.5f * weight_ln[h0];
    const float hl1  = 0.5f * weight_ln[h1];
    const float hsum = hl0 + hl1;
    const float bln  = bias_ln[0];
    const u64 binit0 = pk2(SC * bias[0] + wyt0, 0.f);
    const u64 binit1 = pk2(SC * bias[0] + wyt1, 0.f);

    float z0 = 0.f, z1 = 0.f;
    float t0s = -1.f, t1s = -1.f;    // t = 2s-1; s_init = 0 -> t = -1

    auto issue = [&](int tb, int st) {
#pragma unroll
        for (int r = 0; r < 2; r++) {
            int slot = lane + r * 32;
            int row = slot >> 2, q = slot & 3;
            int t = min(tb + row, B - 1);
            cpa16((unsigned)__cvta_generic_to_shared(&xs[w][st][row][q * 4]),
                  x + (size_t)t * 64 + q * 4);
        }
    };

    // matvec from registers (first half P=qa,qb prefetched; qc,qd fresh)
    auto matvecR = [&](ulonglong2 qa, ulonglong2 qb, ulonglong2 qc, ulonglong2 qd,
                       float& m0, float& m1) {
        u64 c0 = binit0, c1 = binit1;
        c0 = fma2(qa.x, w0k[0], c0);  c1 = fma2(qa.x, w1k[0], c1);
        c0 = fma2(qa.y, w0k[1], c0);  c1 = fma2(qa.y, w1k[1], c1);
        c0 = fma2(qb.x, w0k[2], c0);  c1 = fma2(qb.x, w1k[2], c1);
        c0 = fma2(qb.y, w0k[3], c0);  c1 = fma2(qb.y, w1k[3], c1);
        c0 = fma2(qc.x, w0k[4], c0);  c1 = fma2(qc.x, w1k[4], c1);
        c0 = fma2(qc.y, w0k[5], c0);  c1 = fma2(qc.y, w1k[5], c1);
        c0 = fma2(qd.x, w0k[6], c0);  c1 = fma2(qd.x, w1k[6], c1);
        c0 = fma2(qd.y, w0k[7], c0);  c1 = fma2(qd.y, w1k[7], c1);
        float a0, b0, a1, b1;
        unpk2(a0, b0, c0);
        unpk2(a1, b1, c1);
        m0 = a0 + b1;
        m1 = a1 + b0;
    };

    // the only serial part (2 FFMA + 2 TANH + partial store)
    auto recur = [&](float m0, float m1, int st, int j) {
        z0 = fmaf(wyt0, t0s, m0);
        z1 = fmaf(wyt1, t1s, m1);
        t0s = ftanh(z0);
        t1s = ftanh(z1);
        ps[w][st][j][lane] = fmaf(hl1, t1s, fmaf(hl0, t0s, hsum));
    };

    // Prologue: tile 0 in smem
    issue(t0, 0);
    cpacommit();
    cpawait0();
    __syncwarp();

    // Pipeline invariant entering each full tile:
    //   m  = matvec(row 0 of this tile)
    //   Pa,Pb = first half of row 1 of this tile
    float m0, m1;
    ulonglong2 Pa, Pb;
    {
        const ulonglong2* r0 = (const ulonglong2*)(&xs[w][0][0][0]);
        ulonglong2 qa = r0[0], qb = r0[1], qc = r0[2], qd = r0[3];
        matvecR(qa, qb, qc, qd, m0, m1);
        const ulonglong2* r1 = (const ulonglong2*)(&xs[w][0][1][0]);
        Pa = r1[0]; Pb = r1[1];
    }

    int tb = t0;
    const int jj   = lane & 15;
    const int half = lane >> 4;

    for (int k = 0; k < nt; k++) {
        const int st = k & 1;
        if (k + 1 < nt) { issue(tb + 16, st ^ 1); cpacommit(); }

        const int n = min(16, tstop - tb);
        const float (*xa)[16] = xs[w][st];

        if (n == 16) {
#pragma unroll
            for (int j = 0; j < 16; j++) {
                float n0, n1;
                if (j < 15) {
                    // second half of row j+1 (consumed 8 fma2 below)
                    const ulonglong2* rn = (const ulonglong2*)(&xa[j + 1][8]);
                    ulonglong2 qc = rn[0], qd = rn[1];
                    // first half of row j+2 (consumed next iteration)
                    ulonglong2 Na, Nb;
                    if (j < 14) {
                        const ulonglong2* rp = (const ulonglong2*)(&xa[j + 2][0]);
                        Na = rp[0]; Nb = rp[1];
                    }
                    matvecR(Pa, Pb, qc, qd, n0, n1);
                    if (j < 14) { Pa = Na; Pb = Nb; }
                }
                recur(m0, m1, st, j);          // independent of the matvec above
                if (j < 15) { m0 = n0; m1 = n1; }
            }
        } else {
            // edge tile (last, partial): simple non-pipelined path
            for (int j = 0; j < n; j++) {
                const ulonglong2* rr = (const ulonglong2*)(&xa[j][0]);
                float e0, e1;
                matvecR(rr[0], rr[1], rr[2], rr[3], e0, e1);
                recur(e0, e1, st, j);
            }
        }
        __syncwarp();

        // Reduce: lane (half, jj) sums 16 partials of step tb+jj; combine halves
        {
            const float4* pr = (const float4*)(&ps[w][st][jj][half * 16]);
            float4 a0 = pr[0], a1 = pr[1], a2 = pr[2], a3 = pr[3];
            float r0 = ((a0.x + a0.y) + (a0.z + a0.w)) + ((a1.x + a1.y) + (a1.z + a1.w));
            float r1 = ((a2.x + a2.y) + (a2.z + a2.w)) + ((a3.x + a3.y) + (a3.z + a3.w));
            float r = r0 + r1;
            r += __shfl_xor_sync(0xffffffffu, r, 16);
            int t = tb + jj;
            if (half == 0 && t >= start && t < tstop)
                out[t] = bln + r;
        }
        // next tile writes ps stage st^1: no sync needed (double-buffered)

        if (k + 1 < nt) {
            cpawait0();
            __syncwarp();
            // re-establish pipeline invariant for next tile
            const ulonglong2* r0n = (const ulonglong2*)(&xs[w][st ^ 1][0][0]);
            ulonglong2 qa = r0n[0], qb = r0n[1], qc = r0n[2], qd = r0n[3];
            matvecR(qa, qb, qc, qd, m0, m1);
            const ulonglong2* r1n = (const ulonglong2*)(&xs[w][st ^ 1][1][0]);
            Pa = r1n[0]; Pb = r1n[1];
        }
        tb += 16;
    }

    // Unique last chunk writes final carries: y_h = 2z, y_hs = 0.5 + 0.5*t
    if (start + L >= B) {
        *(float2*)(out + B + 2 * lane) = make_float2(2.f * z0, 2.f * z1);
        *(float2*)(out + B + 64 + 2 * lane) =
            make_float2(fmaf(0.5f, t0s, 0.5f), fmaf(0.5f, t1s, 0.5f));
    }
}

extern "C" void kernel_launch(void* const* d_in, const int* in_sizes, int n_in,
                              void* d_out, int out_size)
{
    const float* x   = (const float*)d_in[0];
    const float* wt  = (const float*)d_in[1];
    const float* wy  = (const float*)d_in[2];
    const float* b   = (const float*)d_in[3];
    const float* wln = (const float*)d_in[4];
    const float* bln = (const float*)d_in[5];
    float* out = (float*)d_out;

    const int B = in_sizes[0] / 64;              // x is (B, T=4, I=16); row stride 64
    const int L = (B + NWARPS - 1) / NWARPS;     // steps per chunk

    rnn_scan_kernel<<<NBLOCKS, BLOCK>>>(x, wt, wy, b, wln, bln, out, B, L);
}

// round 9
// speedup vs baseline: 1.0338x; 1.0338x over previous
#include <cuda_runtime.h>

#define BLOCK   128
#define WPB     4
#define NSM     152
#define OCC     7
#define NBLOCKS (NSM * OCC)          // 1064
#define NWARPS  (NBLOCKS * WPB)      // 4256 chunks, 1 per warp
#define WARM    8
#define PSP     36

typedef unsigned long long u64;

__device__ __forceinline__ u64 pk2(float a, float b) {
    u64 r; asm("mov.b64 %0, {%1,%2};" : "=l"(r) : "f"(a), "f"(b)); return r;
}
__device__ __forceinline__ void unpk2(float& a, float& b, u64 r) {
    asm("mov.b64 {%0,%1}, %2;" : "=f"(a), "=f"(b) : "l"(r));
}
__device__ __forceinline__ u64 fma2(u64 a, u64 b, u64 c) {
    u64 d; asm("fma.rn.f32x2 %0, %1, %2, %3;" : "=l"(d) : "l"(a), "l"(b), "l"(c)); return d;
}
__device__ __forceinline__ float ftanh(float x) {
    float r; asm("tanh.approx.f32 %0, %1;" : "=f"(r) : "f"(x)); return r;
}
__device__ __forceinline__ void cpa16(unsigned d, const void* s) {
    asm volatile("cp.async.ca.shared.global [%0], [%1], 16;" :: "r"(d), "l"(s));
}
__device__ __forceinline__ void cpacommit() { asm volatile("cp.async.commit_group;"); }
__device__ __forceinline__ void cpawait0()  { asm volatile("cp.async.wait_group 0;"); }

__global__ void __launch_bounds__(BLOCK, OCC) rnn_scan_kernel(
    const float* __restrict__ x, const float* __restrict__ weight,
    const float* __restrict__ weight_y, const float* __restrict__ bias,
    const float* __restrict__ weight_ln, const float* __restrict__ bias_ln,
    float* __restrict__ out, int B, int L)
{
    __shared__ __align__(16) float xs[WPB][2][16][16];    // x tiles, double-buffered
    __shared__ __align__(16) float ps[WPB][2][16][PSP];   // partials, double-buffered

    const int w    = threadIdx.x >> 5;
    const int lane = threadIdx.x & 31;
    const int wid  = blockIdx.x * WPB + w;
    const int start = wid * L;
    if (start >= B) return;
    const int tstop = min(start + L, B);
    const int t0    = max(0, start - WARM);   // contraction warmup (<=0.25^8)
    const int nt    = (tstop - t0 + 15) >> 4;

    // sigma(y) = 0.5 + 0.5*tanh(y/2); z = y/2; state t = tanh(z):
    //   z = (0.5*bias + 0.25*wy_h) + x·(0.5 W) + (0.25*wy_h)*t
    const float SC = 0.5f;

    // Lane owns hidden (h0,h1)=(2l,2l+1); crossed-half chains: x multiplier is
    // the natural pair {x_2k,x_2k+1}: z[h0]=c0.lo+c1.hi, z[h1]=c1.lo+c0.hi.
    const int h0 = 2 * lane, h1 = 2 * lane + 1;
    u64 w0k[8], w1k[8];
#pragma unroll
    for (int k = 0; k < 8; k++) {
        const float* r0 = weight + (2 * k) * 64;
        const float* r1 = weight + (2 * k + 1) * 64;
        w0k[k] = pk2(SC * r0[h0], SC * r1[h1]);
        w1k[k] = pk2(SC * r0[h1], SC * r1[h0]);
    }
    const float wyt0 = 0.25f * weight_y[h0];
    const float wyt1 = 0.25f * weight_y[h1];
    const float hl0  = 0.5f * weight_ln[h0];
    const float hl1  = 0.5f * weight_ln[h1];
    const float hsum = hl0 + hl1;
    const float bln  = bias_ln[0];
    const u64 binit0 = pk2(SC * bias[0] + wyt0, 0.f);
    const u64 binit1 = pk2(SC * bias[0] + wyt1, 0.f);

    float z0 = 0.f, z1 = 0.f;
    float t0s = -1.f, t1s = -1.f;    // t = 2s-1; s_init = 0 -> t = -1

    auto issue = [&](int tb, int st) {
#pragma unroll
        for (int r = 0; r < 2; r++) {
            int slot = lane + r * 32;
            int row = slot >> 2, q = slot & 3;
            int t = min(tb + row, B - 1);
            cpa16((unsigned)__cvta_generic_to_shared(&xs[w][st][row][q * 4]),
                  x + (size_t)t * 64 + q * 4);
        }
    };

    auto matvecR = [&](ulonglong2 qa, ulonglong2 qb, ulonglong2 qc, ulonglong2 qd,
                       float& m0, float& m1) {
        u64 c0 = binit0, c1 = binit1;
        c0 = fma2(qa.x, w0k[0], c0);  c1 = fma2(qa.x, w1k[0], c1);
        c0 = fma2(qa.y, w0k[1], c0);  c1 = fma2(qa.y, w1k[1], c1);
        c0 = fma2(qb.x, w0k[2], c0);  c1 = fma2(qb.x, w1k[2], c1);
        c0 = fma2(qb.y, w0k[3], c0);  c1 = fma2(qb.y, w1k[3], c1);
        c0 = fma2(qc.x, w0k[4], c0);  c1 = fma2(qc.x, w1k[4], c1);
        c0 = fma2(qc.y, w0k[5], c0);  c1 = fma2(qc.y, w1k[5], c1);
        c0 = fma2(qd.x, w0k[6], c0);  c1 = fma2(qd.x, w1k[6], c1);
        c0 = fma2(qd.y, w0k[7], c0);  c1 = fma2(qd.y, w1k[7], c1);
        float a0, b0, a1, b1;
        unpk2(a0, b0, c0);
        unpk2(a1, b1, c1);
        m0 = a0 + b1;
        m1 = a1 + b0;
    };

    // the only serial part (2 FFMA + 2 TANH + partial store)
    auto recur = [&](float m0, float m1, int st, int j) {
        z0 = fmaf(wyt0, t0s, m0);
        z1 = fmaf(wyt1, t1s, m1);
        t0s = ftanh(z0);
        t1s = ftanh(z1);
        ps[w][st][j][lane] = fmaf(hl1, t1s, fmaf(hl0, t0s, hsum));
    };

    const int jj   = lane & 15;
    const int half = lane >> 4;

    // reduce stage st_ (tile based at tb_): latency hides under next tile's fma stream
    auto reducePS = [&](int st_, int tb_) {
        const float4* pr = (const float4*)(&ps[w][st_][jj][half * 16]);
        float4 a0 = pr[0], a1 = pr[1], a2 = pr[2], a3 = pr[3];
        float r0 = ((a0.x + a0.y) + (a0.z + a0.w)) + ((a1.x + a1.y) + (a1.z + a1.w));
        float r1 = ((a2.x + a2.y) + (a2.z + a2.w)) + ((a3.x + a3.y) + (a3.z + a3.w));
        float r = r0 + r1;
        r += __shfl_xor_sync(0xffffffffu, r, 16);
        int t = tb_ + jj;
        if (half == 0 && t >= start && t < tstop)
            out[t] = bln + r;
    };

    // Prologue: tile 0 in smem
    issue(t0, 0);
    cpacommit();
    cpawait0();
    __syncwarp();

    // Pipeline invariant entering each full tile:
    //   m = matvec(row 0); m of step j computed during step j-1
    float m0, m1;
    {
        const ulonglong2* r0 = (const ulonglong2*)(&xs[w][0][0][0]);
        matvecR(r0[0], r0[1], r0[2], r0[3], m0, m1);
    }

    int tb = t0;

    for (int k = 0; k < nt; k++) {
        const int st = k & 1;
        if (k + 1 < nt) { issue(tb + 16, st ^ 1); cpacommit(); }

        const int n = min(16, tstop - tb);
        const float (*xa)[16] = xs[w][st];

        if (n == 16) {
#pragma unroll
            for (int j = 0; j < 16; j++) {
                float n0, n1;
                if (j < 15) {
                    const ulonglong2* rn = (const ulonglong2*)(&xa[j + 1][0]);
                    matvecR(rn[0], rn[1], rn[2], rn[3], n0, n1);
                }
                recur(m0, m1, st, j);      // independent of the matvec above
                if (j == 2 && k > 0)       // previous tile's reduce, latency-hidden
                    reducePS(st ^ 1, tb - 16);
                if (j < 15) { m0 = n0; m1 = n1; }
            }
        } else {
            if (k > 0) reducePS(st ^ 1, tb - 16);
            for (int j = 0; j < n; j++) {
                const ulonglong2* rr = (const ulonglong2*)(&xa[j][0]);
                float e0, e1;
                matvecR(rr[0], rr[1], rr[2], rr[3], e0, e1);
                recur(e0, e1, st, j);
            }
        }

        if (k + 1 < nt) {
            cpawait0();
            __syncwarp();   // orders this tile's ps STS before next tile's reduce
            const ulonglong2* r0n = (const ulonglong2*)(&xs[w][st ^ 1][0][0]);
            matvecR(r0n[0], r0n[1], r0n[2], r0n[3], m0, m1);
        }
        tb += 16;
    }

    // Final tile's reduce
    __syncwarp();
    reducePS((nt - 1) & 1, tb - 16);

    // Unique last chunk writes final carries: y_h = 2z, y_hs = 0.5 + 0.5*t
    if (start + L >= B) {
        *(float2*)(out + B + 2 * lane) = make_float2(2.f * z0, 2.f * z1);
        *(float2*)(out + B + 64 + 2 * lane) =
            make_float2(fmaf(0.5f, t0s, 0.5f), fmaf(0.5f, t1s, 0.5f));
    }
}

extern "C" void kernel_launch(void* const* d_in, const int* in_sizes, int n_in,
                              void* d_out, int out_size)
{
    const float* x   = (const float*)d_in[0];
    const float* wt  = (const float*)d_in[1];
    const float* wy  = (const float*)d_in[2];
    const float* b   = (const float*)d_in[3];
    const float* wln = (const float*)d_in[4];
    const float* bln = (const float*)d_in[5];
    float* out = (float*)d_out;

    const int B = in_sizes[0] / 64;              // x is (B, T=4, I=16); row stride 64
    const int L = (B + NWARPS - 1) / NWARPS;     // steps per chunk

    rnn_scan_kernel<<<NBLOCKS, BLOCK>>>(x, wt, wy, b, wln, bln, out, B, L);
}